// round 2
// baseline (speedup 1.0000x reference)
#include <cuda_runtime.h>
#include <math.h>

#define NN    100000      // nodes
#define NE    1600000     // edges
#define NG    512         // graphs
#define INC   64          // in channels
#define HIDC  128         // hidden
#define LATC  64          // latent
#define MN    128         // max nodes
#define NPAIR 8128        // upper-tri pairs

// ---------------- scratch (static device globals; no allocation) ----------------
static __device__ float g_bufH[NN * HIDC];   // GEMM output h = A@W
static __device__ float g_bufA[NN * HIDC];   // aggregated features
static __device__ float g_deg [NN];
static __device__ float g_dinv[NN];
static __device__ float g_sums[NG * HIDC];
static __device__ float g_cnt [NG];
static __device__ float g_p2  [NG * HIDC];
static __device__ unsigned char g_rr[NPAIR];
static __device__ unsigned char g_cc[NPAIR];

// ---------------- helpers ----------------
__device__ __forceinline__ void red_add_v4(float* p, float a, float b, float c, float d) {
    asm volatile("red.global.add.v4.f32 [%0], {%1, %2, %3, %4};"
                 :: "l"(p), "f"(a), "f"(b), "f"(c), "f"(d) : "memory");
}

// ---------------- degree / norm ----------------
__global__ void k_zero_deg() {
    int i = blockIdx.x * blockDim.x + threadIdx.x;
    if (i < NN) g_deg[i] = 0.0f;
}
__global__ void k_deg(const int* __restrict__ ei) {
    int e = blockIdx.x * blockDim.x + threadIdx.x;
    if (e < NE) atomicAdd(&g_deg[ei[NE + e]], 1.0f);
}
__global__ void k_dinv() {
    int i = blockIdx.x * blockDim.x + threadIdx.x;
    if (i < NN) g_dinv[i] = rsqrtf(g_deg[i] + 1.0f);
}

// ---------------- tiled fp32 GEMM, N = 128 fixed ----------------
// C[M,128] = (relu?)A[M,K] @ B[K,128].  128x128 tile, 256 thr, 8x8/thread, BK=16.
template<int K, bool RELU_A>
__global__ __launch_bounds__(256) void k_gemm_n128(
    const float* __restrict__ A, const float* __restrict__ B,
    float* __restrict__ C, int M)
{
    __shared__ float As[16][132];
    __shared__ float Bs[16][128];
    int t = threadIdx.x;
    int tx = t & 15, ty = t >> 4;
    int m0 = blockIdx.x * 128;

    float acc[8][8];
#pragma unroll
    for (int i = 0; i < 8; i++)
#pragma unroll
        for (int j = 0; j < 8; j++) acc[i][j] = 0.0f;

    for (int k0 = 0; k0 < K; k0 += 16) {
#pragma unroll
        for (int l = 0; l < 8; l++) {              // A tile 128x16
            int idx = t + l * 256;
            int row = idx >> 4, kk = idx & 15;
            int gr = m0 + row;
            float v = (gr < M) ? A[gr * K + k0 + kk] : 0.0f;
            if (RELU_A) v = fmaxf(v, 0.0f);
            As[kk][row] = v;
        }
#pragma unroll
        for (int l = 0; l < 8; l++) {              // B tile 16x128
            int idx = t + l * 256;
            int kk = idx >> 7, n = idx & 127;
            Bs[kk][n] = B[(k0 + kk) * 128 + n];
        }
        __syncthreads();
#pragma unroll
        for (int kk = 0; kk < 16; kk++) {
            float a[8], b[8];
#pragma unroll
            for (int i = 0; i < 8; i++) a[i] = As[kk][ty * 8 + i];
#pragma unroll
            for (int j = 0; j < 8; j++) b[j] = Bs[kk][tx * 8 + j];
#pragma unroll
            for (int i = 0; i < 8; i++)
#pragma unroll
                for (int j = 0; j < 8; j++)
                    acc[i][j] = fmaf(a[i], b[j], acc[i][j]);
        }
        __syncthreads();
    }
#pragma unroll
    for (int i = 0; i < 8; i++) {
        int gr = m0 + ty * 8 + i;
        if (gr < M) {
#pragma unroll
            for (int j = 0; j < 8; j++)
                C[gr * 128 + tx * 8 + j] = acc[i][j];
        }
    }
}

// ---------------- agg init: agg = h * dinv^2 + bias ----------------
__global__ void k_agg_init(const float* __restrict__ bias) {
    int idx = blockIdx.x * blockDim.x + threadIdx.x;   // NN*32 float4 slots
    if (idx >= NN * 32) return;
    int node = idx >> 5, q = idx & 31;
    float d = g_dinv[node];
    float d2 = d * d;
    float4 h = ((const float4*)g_bufH)[idx];
    float4 bb = ((const float4*)bias)[q];
    float4 o;
    o.x = fmaf(h.x, d2, bb.x);
    o.y = fmaf(h.y, d2, bb.y);
    o.z = fmaf(h.z, d2, bb.z);
    o.w = fmaf(h.w, d2, bb.w);
    ((float4*)g_bufA)[idx] = o;
}

// ---------------- edge scatter: one warp per edge, vec4 L2 reductions ----------------
__global__ __launch_bounds__(256) void k_scatter(const int* __restrict__ ei) {
    int gtid = blockIdx.x * blockDim.x + threadIdx.x;
    int e    = gtid >> 5;
    int lane = gtid & 31;
    if (e >= NE) return;
    int src = __ldg(&ei[e]);
    int dst = __ldg(&ei[NE + e]);
    float norm = g_dinv[src] * g_dinv[dst];
    float4 v = __ldg(((const float4*)g_bufH) + src * 32 + lane);
    red_add_v4(g_bufA + dst * 128 + lane * 4,
               v.x * norm, v.y * norm, v.z * norm, v.w * norm);
}

// ---------------- pooling ----------------
__global__ void k_zero_pool() {
    int i = blockIdx.x * blockDim.x + threadIdx.x;
    if (i < NG * HIDC) g_sums[i] = 0.0f;
    if (i < NG) g_cnt[i] = 0.0f;
}
__global__ void k_pool(const int* __restrict__ batch) {
    int idx = blockIdx.x * blockDim.x + threadIdx.x;   // NN*32 float4 slots
    if (idx >= NN * 32) return;
    int node = idx >> 5, q = idx & 31;
    int g = batch[node];
    float4 v = ((const float4*)g_bufA)[idx];
    red_add_v4(g_sums + g * 128 + q * 4,
               fmaxf(v.x, 0.0f), fmaxf(v.y, 0.0f),
               fmaxf(v.z, 0.0f), fmaxf(v.w, 0.0f));
    if (q == 0) atomicAdd(&g_cnt[g], 1.0f);
}

// ---------------- per-graph head: mean, mu/logvar, reparam, MLP x2 ----------------
__global__ __launch_bounds__(128) void k_head(
    const float* __restrict__ eps,
    const float* __restrict__ Wmu, const float* __restrict__ bmu,
    const float* __restrict__ Wlv, const float* __restrict__ blv,
    const float* __restrict__ D1,  const float* __restrict__ d1,
    const float* __restrict__ D2,  const float* __restrict__ d2,
    float* __restrict__ out_mu, float* __restrict__ out_lv)
{
    int g = blockIdx.x, t = threadIdx.x;
    __shared__ float hg[HIDC], z[LATC], p1[HIDC];
    float cnt = fmaxf(g_cnt[g], 1.0f);
    hg[t] = g_sums[g * HIDC + t] / cnt;
    __syncthreads();
    if (t < LATC) {
        float mu = bmu[t], lv = blv[t];
#pragma unroll 8
        for (int c = 0; c < HIDC; c++) {
            float h = hg[c];
            mu = fmaf(h, Wmu[c * LATC + t], mu);
            lv = fmaf(h, Wlv[c * LATC + t], lv);
        }
        out_mu[g * LATC + t] = mu;
        out_lv[g * LATC + t] = lv;
        z[t] = mu + eps[g * LATC + t] * expf(0.5f * lv);
    }
    __syncthreads();
    {
        float a = d1[t];
#pragma unroll 8
        for (int k = 0; k < LATC; k++) a = fmaf(z[k], D1[k * HIDC + t], a);
        p1[t] = fmaxf(a, 0.0f);
    }
    __syncthreads();
    {
        float a = d2[t];
#pragma unroll 8
        for (int k = 0; k < HIDC; k++) a = fmaf(p1[k], D2[k * HIDC + t], a);
        g_p2[g * HIDC + t] = fmaxf(a, 0.0f);
    }
}

// ---------------- triu index LUT ----------------
__global__ void k_rc() {
    int k = blockIdx.x * blockDim.x + threadIdx.x;
    if (k >= NPAIR) return;
    int r = 0, rem = k;
    while (rem >= MN - 1 - r) { rem -= MN - 1 - r; r++; }
    g_rr[k] = (unsigned char)r;
    g_cc[k] = (unsigned char)(r + 1 + rem);
}

// ---------------- decoder GEMM + sigmoid + symmetric adjacency write ----------------
// probs[512,8128] = sigmoid(g_p2[512,128] @ D3[128,8128] + d3)
__global__ __launch_bounds__(256) void k_dec(
    const float* __restrict__ D3, const float* __restrict__ d3,
    float* __restrict__ adj)
{
    __shared__ float As[16][132];
    __shared__ float Bs[16][128];
    int t = threadIdx.x;
    int tx = t & 15, ty = t >> 4;
    int m0 = blockIdx.y * 128;
    int n0 = blockIdx.x * 128;

    float acc[8][8];
#pragma unroll
    for (int i = 0; i < 8; i++)
#pragma unroll
        for (int j = 0; j < 8; j++) acc[i][j] = 0.0f;

    for (int k0 = 0; k0 < HIDC; k0 += 16) {
#pragma unroll
        for (int l = 0; l < 8; l++) {
            int idx = t + l * 256;
            int row = idx >> 4, kk = idx & 15;
            As[kk][row] = g_p2[(m0 + row) * HIDC + k0 + kk];
        }
#pragma unroll
        for (int l = 0; l < 8; l++) {
            int idx = t + l * 256;
            int kk = idx >> 7, n = idx & 127;
            int gn = n0 + n;
            Bs[kk][n] = (gn < NPAIR) ? D3[(k0 + kk) * NPAIR + gn] : 0.0f;
        }
        __syncthreads();
#pragma unroll
        for (int kk = 0; kk < 16; kk++) {
            float a[8], b[8];
#pragma unroll
            for (int i = 0; i < 8; i++) a[i] = As[kk][ty * 8 + i];
#pragma unroll
            for (int j = 0; j < 8; j++) b[j] = Bs[kk][tx * 8 + j];
#pragma unroll
            for (int i = 0; i < 8; i++)
#pragma unroll
                for (int j = 0; j < 8; j++)
                    acc[i][j] = fmaf(a[i], b[j], acc[i][j]);
        }
        __syncthreads();
    }
#pragma unroll
    for (int i = 0; i < 8; i++) {
        int g = m0 + ty * 8 + i;          // always < 512
#pragma unroll
        for (int j = 0; j < 8; j++) {
            int n = n0 + tx * 8 + j;
            if (n < NPAIR) {
                float v = acc[i][j] + d3[n];
                v = 1.0f / (1.0f + expf(-v));
                int r = g_rr[n], c = g_cc[n];
                int base = g << 14;       // g * 128*128
                adj[base + (r << 7) + c] = v;
                adj[base + (c << 7) + r] = v;
            }
        }
    }
}

__global__ void k_diag(float* __restrict__ adj) {
    int idx = blockIdx.x * blockDim.x + threadIdx.x;
    if (idx < NG * MN) {
        int g = idx >> 7, i = idx & 127;
        adj[(g << 14) + (i << 7) + i] = 0.0f;
    }
}

// ---------------- launch ----------------
extern "C" void kernel_launch(void* const* d_in, const int* in_sizes, int n_in,
                              void* d_out, int out_size)
{
    const float* x     = (const float*)d_in[0];
    const int*   ei    = (const int*)  d_in[1];
    const int*   batch = (const int*)  d_in[2];
    const float* eps   = (const float*)d_in[3];
    const float* W1    = (const float*)d_in[4];
    const float* b1    = (const float*)d_in[5];
    const float* W2    = (const float*)d_in[6];
    const float* b2    = (const float*)d_in[7];
    const float* Wmu   = (const float*)d_in[8];
    const float* bmu   = (const float*)d_in[9];
    const float* Wlv   = (const float*)d_in[10];
    const float* blv   = (const float*)d_in[11];
    const float* D1    = (const float*)d_in[12];
    const float* d1    = (const float*)d_in[13];
    const float* D2    = (const float*)d_in[14];
    const float* d2    = (const float*)d_in[15];
    const float* D3    = (const float*)d_in[16];
    const float* d3    = (const float*)d_in[17];

    float* out    = (float*)d_out;
    float* adj    = out;                                   // 512*128*128
    float* out_mu = out + (size_t)NG * MN * MN;            // 512*64
    float* out_lv = out_mu + (size_t)NG * LATC;            // 512*64

    void *pH = 0, *pA = 0;
    cudaGetSymbolAddress(&pH, g_bufH);
    cudaGetSymbolAddress(&pA, g_bufA);

    const int T = 256;

    // degrees / norms
    k_zero_deg<<<(NN + T - 1) / T, T>>>();
    k_deg     <<<(NE + T - 1) / T, T>>>(ei);
    k_dinv    <<<(NN + T - 1) / T, T>>>();

    // layer 1: h = x @ W1 ; agg = scatter + self + b1
    k_gemm_n128<INC, false><<<(NN + 127) / 128, T>>>(x, W1, (float*)pH, NN);
    k_agg_init<<<(NN * 32 + T - 1) / T, T>>>(b1);
    k_scatter <<<(NE * 32) / T, T>>>(ei);

    // layer 2: h = relu(agg) @ W2 ; agg = scatter + self + b2
    k_gemm_n128<HIDC, true><<<(NN + 127) / 128, T>>>((const float*)pA, W2, (float*)pH, NN);
    k_agg_init<<<(NN * 32 + T - 1) / T, T>>>(b2);
    k_scatter <<<(NE * 32) / T, T>>>(ei);

    // pooling (relu fused)
    k_zero_pool<<<(NG * HIDC + T - 1) / T, T>>>();
    k_pool     <<<(NN * 32 + T - 1) / T, T>>>(batch);

    // per-graph head: mean, mu/logvar, reparam, MLP1, MLP2
    k_head<<<NG, 128>>>(eps, Wmu, bmu, Wlv, blv, D1, d1, D2, d2, out_mu, out_lv);

    // decoder + adjacency
    k_rc  <<<(NPAIR + T - 1) / T, T>>>();
    k_dec <<<dim3((NPAIR + 127) / 128, NG / 128), T>>>(D3, d3, adj);
    k_diag<<<(NG * MN + T - 1) / T, T>>>(adj);
}

// round 4
// speedup vs baseline: 1.5226x; 1.5226x over previous
#include <cuda_runtime.h>
#include <math.h>

#define NN    100000      // nodes
#define NE    1600000     // edges
#define NG    512         // graphs
#define INC   64          // in channels
#define HIDC  128         // hidden
#define LATC  64          // latent
#define MN    128         // max nodes
#define NPAIR 8128        // upper-tri pairs

// ---------------- scratch (static device globals; no allocation) ----------------
static __device__ float g_bufH[NN * HIDC];   // GEMM output h = A@W
static __device__ float g_bufA[NN * HIDC];   // aggregated (relu'd) features
static __device__ float g_dinv[NN];
static __device__ int   g_degi[NN];
static __device__ int   g_off [NN + 1];
static __device__ int   g_cur [NN];
static __device__ int   g_csr [NE];
static __device__ int   g_start[NG + 1];
static __device__ float g_sums[NG * HIDC];   // per-graph mean
static __device__ float g_p2  [NG * HIDC];
static __device__ unsigned char g_rr[NPAIR];
static __device__ unsigned char g_cc[NPAIR];

// ---------------- degree / norm ----------------
__global__ void k_zero_deg() {
    int i = blockIdx.x * blockDim.x + threadIdx.x;
    if (i < NN) g_degi[i] = 0;
}
__global__ void k_deg(const int* __restrict__ ei) {
    int e = blockIdx.x * blockDim.x + threadIdx.x;
    if (e < NE) atomicAdd(&g_degi[ei[NE + e]], 1);
}
__global__ void k_dinv() {
    int i = blockIdx.x * blockDim.x + threadIdx.x;
    if (i < NN) g_dinv[i] = rsqrtf((float)g_degi[i] + 1.0f);
}

// ---------------- single-block exclusive scan of g_degi -> g_off, g_cur ----------------
__global__ __launch_bounds__(1024) void k_scan() {
    __shared__ int wsum[32];
    __shared__ int carry_s;
    __shared__ int btot;
    int t = threadIdx.x, lane = t & 31, wid = t >> 5;
    if (t == 0) carry_s = 0;
    __syncthreads();
    for (int base = 0; base < NN; base += 1024) {
        int i = base + t;
        int v = (i < NN) ? g_degi[i] : 0;
        int incl = v;
#pragma unroll
        for (int d = 1; d < 32; d <<= 1) {
            int n = __shfl_up_sync(0xffffffffu, incl, d);
            if (lane >= d) incl += n;
        }
        if (lane == 31) wsum[wid] = incl;
        __syncthreads();
        if (wid == 0) {
            int x = wsum[lane];
            int xi = x;
#pragma unroll
            for (int d = 1; d < 32; d <<= 1) {
                int n = __shfl_up_sync(0xffffffffu, xi, d);
                if (lane >= d) xi += n;
            }
            wsum[lane] = xi - x;
            if (lane == 31) btot = xi;
        }
        __syncthreads();
        int excl = incl - v + wsum[wid] + carry_s;
        if (i < NN) { g_off[i] = excl; g_cur[i] = excl; }
        __syncthreads();
        if (t == 0) carry_s += btot;
        __syncthreads();
    }
    if (t == 0) g_off[NN] = carry_s;
}

// ---------------- fill dst-CSR ----------------
__global__ void k_fill(const int* __restrict__ ei) {
    int e = blockIdx.x * blockDim.x + threadIdx.x;
    if (e >= NE) return;
    int src = ei[e], dst = ei[NE + e];
    int pos = atomicAdd(&g_cur[dst], 1);
    g_csr[pos] = src;
}

// ---------------- graph boundaries (batch is sorted) ----------------
__global__ void k_bounds(const int* __restrict__ batch) {
    int g = blockIdx.x * blockDim.x + threadIdx.x;
    if (g > NG) return;
    if (g == NG) { g_start[NG] = NN; return; }
    int lo = 0, hi = NN;
    while (lo < hi) {
        int mid = (lo + hi) >> 1;
        if (batch[mid] < g) lo = mid + 1; else hi = mid;
    }
    g_start[g] = lo;
}

// ---------------- double-buffered fp32 GEMM, N = 128 fixed ----------------
// C[M,128] = A[M,K] @ B[K,128].  128x128 tile, 256 thr, 8x8/thread, BK=16.
template<int K>
__global__ __launch_bounds__(256) void k_gemm_n128(
    const float* __restrict__ A, const float* __restrict__ B,
    float* __restrict__ C, int M)
{
    __shared__ float As[2][16][132];
    __shared__ float Bs[2][16][128];
    int t = threadIdx.x;
    int tx = t & 15, ty = t >> 4;
    int m0 = blockIdx.x * 128;
    int arow = t >> 4, akk = t & 15;       // A element [arow + 16l][akk]
    int bkk0 = t >> 7, bn = t & 127;       // B element [bkk0 + 2l][bn]

    float acc[8][8];
#pragma unroll
    for (int i = 0; i < 8; i++)
#pragma unroll
        for (int j = 0; j < 8; j++) acc[i][j] = 0.0f;

    float ra[8], rb[8];
    // prologue: load tile k0=0
#pragma unroll
    for (int l = 0; l < 8; l++) {
        int gr = m0 + arow + l * 16;
        ra[l] = (gr < M) ? A[(size_t)gr * K + akk] : 0.0f;
        rb[l] = B[(bkk0 + l * 2) * 128 + bn];
    }
#pragma unroll
    for (int l = 0; l < 8; l++) {
        As[0][akk][arow + l * 16] = ra[l];
        Bs[0][bkk0 + l * 2][bn] = rb[l];
    }
    __syncthreads();

    int buf = 0;
    for (int k0 = 0; k0 < K; k0 += 16) {
        int nk = k0 + 16;
        if (nk < K) {
#pragma unroll
            for (int l = 0; l < 8; l++) {
                int gr = m0 + arow + l * 16;
                ra[l] = (gr < M) ? A[(size_t)gr * K + nk + akk] : 0.0f;
                rb[l] = B[(nk + bkk0 + l * 2) * 128 + bn];
            }
        }
#pragma unroll
        for (int kk = 0; kk < 16; kk++) {
            float a[8], b[8];
#pragma unroll
            for (int i = 0; i < 8; i++) a[i] = As[buf][kk][ty * 8 + i];
#pragma unroll
            for (int j = 0; j < 8; j++) b[j] = Bs[buf][kk][tx * 8 + j];
#pragma unroll
            for (int i = 0; i < 8; i++)
#pragma unroll
                for (int j = 0; j < 8; j++)
                    acc[i][j] = fmaf(a[i], b[j], acc[i][j]);
        }
        if (nk < K) {
#pragma unroll
            for (int l = 0; l < 8; l++) {
                As[buf ^ 1][akk][arow + l * 16] = ra[l];
                Bs[buf ^ 1][bkk0 + l * 2][bn] = rb[l];
            }
            __syncthreads();
            buf ^= 1;
        }
    }
#pragma unroll
    for (int i = 0; i < 8; i++) {
        int gr = m0 + ty * 8 + i;
        if (gr < M) {
#pragma unroll
            for (int j = 0; j < 8; j++)
                C[(size_t)gr * 128 + tx * 8 + j] = acc[i][j];
        }
    }
}

// ---------------- CSR gather: agg = relu( sum_in h[src]*norm + h[dst]*dinv^2 + bias ) ----------------
// one warp per dst node, lane = float4 channel slot
__global__ __launch_bounds__(256) void k_gather(const float* __restrict__ bias) {
    int w    = (blockIdx.x * blockDim.x + threadIdx.x) >> 5;
    int lane = threadIdx.x & 31;
    if (w >= NN) return;
    int s = g_off[w], e = g_off[w + 1];
    float dv = g_dinv[w];
    float4 h  = __ldg(((const float4*)g_bufH) + (size_t)w * 32 + lane);
    float4 bb = __ldg(((const float4*)bias) + lane);
    float d2 = dv * dv;
    float4 acc;
    acc.x = fmaf(h.x, d2, bb.x);
    acc.y = fmaf(h.y, d2, bb.y);
    acc.z = fmaf(h.z, d2, bb.z);
    acc.w = fmaf(h.w, d2, bb.w);

    int k = s;
    for (; k + 1 < e; k += 2) {
        int s0 = __ldg(&g_csr[k]);
        int s1 = __ldg(&g_csr[k + 1]);
        float n0 = dv * __ldg(&g_dinv[s0]);
        float n1 = dv * __ldg(&g_dinv[s1]);
        float4 v0 = __ldg(((const float4*)g_bufH) + (size_t)s0 * 32 + lane);
        float4 v1 = __ldg(((const float4*)g_bufH) + (size_t)s1 * 32 + lane);
        acc.x = fmaf(v0.x, n0, acc.x); acc.y = fmaf(v0.y, n0, acc.y);
        acc.z = fmaf(v0.z, n0, acc.z); acc.w = fmaf(v0.w, n0, acc.w);
        acc.x = fmaf(v1.x, n1, acc.x); acc.y = fmaf(v1.y, n1, acc.y);
        acc.z = fmaf(v1.z, n1, acc.z); acc.w = fmaf(v1.w, n1, acc.w);
    }
    if (k < e) {
        int s0 = __ldg(&g_csr[k]);
        float n0 = dv * __ldg(&g_dinv[s0]);
        float4 v0 = __ldg(((const float4*)g_bufH) + (size_t)s0 * 32 + lane);
        acc.x = fmaf(v0.x, n0, acc.x); acc.y = fmaf(v0.y, n0, acc.y);
        acc.z = fmaf(v0.z, n0, acc.z); acc.w = fmaf(v0.w, n0, acc.w);
    }
    acc.x = fmaxf(acc.x, 0.0f); acc.y = fmaxf(acc.y, 0.0f);
    acc.z = fmaxf(acc.z, 0.0f); acc.w = fmaxf(acc.w, 0.0f);
    ((float4*)g_bufA)[(size_t)w * 32 + lane] = acc;
}

// ---------------- segmented mean pool (batch sorted; relu already applied) ----------------
__global__ __launch_bounds__(512) void k_pool2() {
    int g = blockIdx.x, t = threadIdx.x;
    int c = t & 127, sub = t >> 7;             // 4 node-lanes
    int s = g_start[g], e = g_start[g + 1];
    float acc = 0.0f;
    for (int n = s + sub; n < e; n += 4)
        acc += g_bufA[(size_t)n * 128 + c];
    __shared__ float red[512];
    red[t] = acc;
    __syncthreads();
    if (sub == 0) {
        float v = red[c] + red[c + 128] + red[c + 256] + red[c + 384];
        float cnt = fmaxf((float)(e - s), 1.0f);
        g_sums[g * 128 + c] = v / cnt;
    }
}

// ---------------- per-graph head: mu/logvar, reparam, MLP x2 ----------------
__global__ __launch_bounds__(128) void k_head(
    const float* __restrict__ eps,
    const float* __restrict__ Wmu, const float* __restrict__ bmu,
    const float* __restrict__ Wlv, const float* __restrict__ blv,
    const float* __restrict__ D1,  const float* __restrict__ d1,
    const float* __restrict__ D2,  const float* __restrict__ d2,
    float* __restrict__ out_mu, float* __restrict__ out_lv)
{
    int g = blockIdx.x, t = threadIdx.x;
    __shared__ float hg[HIDC], z[LATC], p1[HIDC];
    hg[t] = g_sums[g * HIDC + t];
    __syncthreads();
    if (t < LATC) {
        float mu = bmu[t], lv = blv[t];
#pragma unroll 8
        for (int c = 0; c < HIDC; c++) {
            float h = hg[c];
            mu = fmaf(h, Wmu[c * LATC + t], mu);
            lv = fmaf(h, Wlv[c * LATC + t], lv);
        }
        out_mu[g * LATC + t] = mu;
        out_lv[g * LATC + t] = lv;
        z[t] = mu + eps[g * LATC + t] * expf(0.5f * lv);
    }
    __syncthreads();
    {
        float a = d1[t];
#pragma unroll 8
        for (int k = 0; k < LATC; k++) a = fmaf(z[k], D1[k * HIDC + t], a);
        p1[t] = fmaxf(a, 0.0f);
    }
    __syncthreads();
    {
        float a = d2[t];
#pragma unroll 8
        for (int k = 0; k < HIDC; k++) a = fmaf(p1[k], D2[k * HIDC + t], a);
        g_p2[g * HIDC + t] = fmaxf(a, 0.0f);
    }
}

// ---------------- triu index LUT ----------------
__global__ void k_rc() {
    int k = blockIdx.x * blockDim.x + threadIdx.x;
    if (k >= NPAIR) return;
    int r = 0, rem = k;
    while (rem >= MN - 1 - r) { rem -= MN - 1 - r; r++; }
    g_rr[k] = (unsigned char)r;
    g_cc[k] = (unsigned char)(r + 1 + rem);
}

// ---------------- decoder GEMM + sigmoid + symmetric adjacency write ----------------
__global__ __launch_bounds__(256) void k_dec(
    const float* __restrict__ D3, const float* __restrict__ d3,
    float* __restrict__ adj)
{
    __shared__ float As[16][132];
    __shared__ float Bs[16][128];
    int t = threadIdx.x;
    int tx = t & 15, ty = t >> 4;
    int m0 = blockIdx.y * 128;
    int n0 = blockIdx.x * 128;

    float acc[8][8];
#pragma unroll
    for (int i = 0; i < 8; i++)
#pragma unroll
        for (int j = 0; j < 8; j++) acc[i][j] = 0.0f;

    for (int k0 = 0; k0 < HIDC; k0 += 16) {
#pragma unroll
        for (int l = 0; l < 8; l++) {
            int idx = t + l * 256;
            int row = idx >> 4, kk = idx & 15;
            As[kk][row] = g_p2[(m0 + row) * HIDC + k0 + kk];
        }
#pragma unroll
        for (int l = 0; l < 8; l++) {
            int idx = t + l * 256;
            int kk = idx >> 7, n = idx & 127;
            int gn = n0 + n;
            Bs[kk][n] = (gn < NPAIR) ? D3[(size_t)(k0 + kk) * NPAIR + gn] : 0.0f;
        }
        __syncthreads();
#pragma unroll
        for (int kk = 0; kk < 16; kk++) {
            float a[8], b[8];
#pragma unroll
            for (int i = 0; i < 8; i++) a[i] = As[kk][ty * 8 + i];
#pragma unroll
            for (int j = 0; j < 8; j++) b[j] = Bs[kk][tx * 8 + j];
#pragma unroll
            for (int i = 0; i < 8; i++)
#pragma unroll
                for (int j = 0; j < 8; j++)
                    acc[i][j] = fmaf(a[i], b[j], acc[i][j]);
        }
        __syncthreads();
    }
#pragma unroll
    for (int i = 0; i < 8; i++) {
        int g = m0 + ty * 8 + i;
#pragma unroll
        for (int j = 0; j < 8; j++) {
            int n = n0 + tx * 8 + j;
            if (n < NPAIR) {
                float v = acc[i][j] + d3[n];
                v = 1.0f / (1.0f + expf(-v));
                int r = g_rr[n], c = g_cc[n];
                int base = g << 14;
                adj[base + (r << 7) + c] = v;
                adj[base + (c << 7) + r] = v;
            }
        }
    }
}

__global__ void k_diag(float* __restrict__ adj) {
    int idx = blockIdx.x * blockDim.x + threadIdx.x;
    if (idx < NG * MN) {
        int g = idx >> 7, i = idx & 127;
        adj[(g << 14) + (i << 7) + i] = 0.0f;
    }
}

// ---------------- launch ----------------
extern "C" void kernel_launch(void* const* d_in, const int* in_sizes, int n_in,
                              void* d_out, int out_size)
{
    const float* x     = (const float*)d_in[0];
    const int*   ei    = (const int*)  d_in[1];
    const int*   batch = (const int*)  d_in[2];
    const float* eps   = (const float*)d_in[3];
    const float* W1    = (const float*)d_in[4];
    const float* b1    = (const float*)d_in[5];
    const float* W2    = (const float*)d_in[6];
    const float* b2    = (const float*)d_in[7];
    const float* Wmu   = (const float*)d_in[8];
    const float* bmu   = (const float*)d_in[9];
    const float* Wlv   = (const float*)d_in[10];
    const float* blv   = (const float*)d_in[11];
    const float* D1    = (const float*)d_in[12];
    const float* d1    = (const float*)d_in[13];
    const float* D2    = (const float*)d_in[14];
    const float* d2    = (const float*)d_in[15];
    const float* D3    = (const float*)d_in[16];
    const float* d3    = (const float*)d_in[17];

    float* out    = (float*)d_out;
    float* adj    = out;                                   // 512*128*128
    float* out_mu = out + (size_t)NG * MN * MN;            // 512*64
    float* out_lv = out_mu + (size_t)NG * LATC;            // 512*64

    void *pH = 0, *pA = 0;
    cudaGetSymbolAddress(&pH, g_bufH);
    cudaGetSymbolAddress(&pA, g_bufA);

    const int T = 256;

    // degrees / norms / CSR / graph bounds
    k_zero_deg<<<(NN + T - 1) / T, T>>>();
    k_deg     <<<(NE + T - 1) / T, T>>>(ei);
    k_dinv    <<<(NN + T - 1) / T, T>>>();
    k_scan    <<<1, 1024>>>();
    k_fill    <<<(NE + T - 1) / T, T>>>(ei);
    k_bounds  <<<(NG + 1 + T - 1) / T, T>>>(batch);

    // layer 1: h = x @ W1 ; agg = relu(gather + self + b1)
    k_gemm_n128<INC><<<(NN + 127) / 128, T>>>(x, W1, (float*)pH, NN);
    k_gather<<<(NN * 32 + T - 1) / T, T>>>(b1);

    // layer 2: h = agg1 @ W2 ; agg = relu(gather + self + b2)
    k_gemm_n128<HIDC><<<(NN + 127) / 128, T>>>((const float*)pA, W2, (float*)pH, NN);
    k_gather<<<(NN * 32 + T - 1) / T, T>>>(b2);

    // segmented mean pool
    k_pool2<<<NG, 512>>>();

    // per-graph head
    k_head<<<NG, 128>>>(eps, Wmu, bmu, Wlv, blv, D1, d1, D2, d2, out_mu, out_lv);

    // decoder + adjacency
    k_rc  <<<(NPAIR + T - 1) / T, T>>>();
    k_dec <<<dim3((NPAIR + 127) / 128, NG / 128), T>>>(D3, d3, adj);
    k_diag<<<(NG * MN + T - 1) / T, T>>>(adj);
}